// round 9
// baseline (speedup 1.0000x reference)
#include <cuda_runtime.h>
#include <cstdint>

// Problem constants (fixed by the reference)
#define EMB_D   64
#define HID     128
#define KDIM    128
#define TM      64      // batch rows per block -> grid = 256
#define NTHR    256     // 16 tx-groups x 16 ty-groups
#define WP      130     // row pitch (floats): even (8B align), 130 mod 32 = 2 -> conflict-free

typedef unsigned long long u64;

// ---------------- f32x2 helpers (Blackwell packed fp32) ----------------
__device__ __forceinline__ void f2up(u64 v, float& lo, float& hi) {
    asm("mov.b64 {%0, %1}, %2;" : "=f"(lo), "=f"(hi) : "l"(v));
}
__device__ __forceinline__ u64 f2fma(u64 a, u64 b, u64 c) {
    u64 d;
    asm("fma.rn.f32x2 %0, %1, %2, %3;" : "=l"(d) : "l"(a), "l"(b), "l"(c));
    return d;
}

// Smem layout (floats):
//   w1s : HID * WP   transposed weights, w1s[j*WP + k] = w1[j][k]
//   xT  : TM  * WP   gathered inputs row-major, xT[r*WP + k]
//   b1s : HID, w2s : HID, bsu : TM, bsi : TM
#define SM_W1S_F  (HID * WP)
#define SM_XT_F   (TM * WP)
#define SM_FLOATS (SM_W1S_F + SM_XT_F + 2 * HID + 2 * TM)
#define SM_BYTES  (SM_FLOATS * sizeof(float))

extern "C" __global__ void __launch_bounds__(NTHR, 2)
mf_fused_kernel(const int* __restrict__ users,
                const int* __restrict__ items,
                const float* __restrict__ user_emb,
                const float* __restrict__ item_emb,
                const float* __restrict__ user_bias,
                const float* __restrict__ item_bias,
                const float* __restrict__ global_bias,
                const float* __restrict__ w1,
                const float* __restrict__ b1,
                const float* __restrict__ w2,
                const float* __restrict__ b2,
                float* __restrict__ out,
                int B)
{
    extern __shared__ float sm[];
    float* w1s = sm;
    float* xT  = sm + SM_W1S_F;
    float* b1s = xT + SM_XT_F;
    float* w2s = b1s + HID;
    float* bsu = w2s + HID;
    float* bsi = bsu + TM;

    const int tid  = threadIdx.x;
    const int base = blockIdx.x * TM;

    // ---- gather embeddings + per-row biases into smem ----
    // 256 threads = 64 rows x 2 halves x 2 subs; each thread moves 32 floats (128 B)
    {
        int r    = tid >> 2;
        int q    = tid & 3;
        int half = q >> 1;        // 0 = user (k 0..63), 1 = item (k 64..127)
        int sub  = q & 1;
        int row  = base + r;
        int idx  = 0;
        if (row < B) idx = half ? items[row] : users[row];
        const float2* src = (const float2*)((half ? item_emb : user_emb)
                                            + (size_t)idx * EMB_D + sub * 32);
        float2* dst = (float2*)(xT + r * WP + half * EMB_D + sub * 32);
        #pragma unroll
        for (int i = 0; i < 16; i++)
            dst[i] = src[i];
        if (sub == 0) {
            float bv = 0.0f;
            if (row < B) bv = half ? item_bias[idx] : user_bias[idx];
            (half ? bsi : bsu)[r] = bv;
        }
    }

    // ---- stage w1 (row-major [HID][KDIM]) into padded rows, float2 granularity ----
    {
        const float2* w1v = (const float2*)w1;
        #pragma unroll
        for (int i = tid; i < (HID * KDIM) / 2; i += NTHR) {
            int j  = i >> 6;      // 64 float2 per source row
            int k2 = i & 63;
            *(float2*)(w1s + j * WP + 2 * k2) = w1v[i];
        }
    }
    if (tid < HID) { b1s[tid] = b1[tid]; w2s[tid] = w2[tid]; }
    __syncthreads();

    // ---- GEMM mainloop: K split into (even,odd) halves of each f32x2 ----
    // tx = tid&15 owns hidden units j = tx + 16m (m=0..7)
    // ty = tid>>4 (0..15) owns rows r = 4*ty .. 4*ty+3
    const int tx = tid & 15;
    const int ty = tid >> 4;
    const float* wB = w1s + tx * WP;
    const float* xB = xT + (ty * 4) * WP;

    u64 acc[8][4];
    #pragma unroll
    for (int m = 0; m < 8; m++)
        #pragma unroll
        for (int i = 0; i < 4; i++)
            acc[m][i] = 0ull;

    #pragma unroll 2
    for (int k = 0; k < KDIM; k += 2) {
        u64 wv[8], xv[4];
        #pragma unroll
        for (int m = 0; m < 8; m++)
            wv[m] = *(const u64*)(wB + m * (16 * WP) + k);   // (w[j][k], w[j][k+1])
        #pragma unroll
        for (int i = 0; i < 4; i++)
            xv[i] = *(const u64*)(xB + i * WP + k);          // (x[r][k], x[r][k+1])
        #pragma unroll
        for (int m = 0; m < 8; m++)
            #pragma unroll
            for (int i = 0; i < 4; i++)
                acc[m][i] = f2fma(wv[m], xv[i], acc[m][i]);
    }

    // ---- epilogue ----
    // dot(u,v) partials: tx covers emb dims [4tx, 4tx+4) as two k-pairs
    float s[4];
    {
        const int k0 = 4 * tx;
        #pragma unroll
        for (int i = 0; i < 4; i++) {
            const float* xr = xB + i * WP;
            u64 p = f2fma(*(const u64*)(xr + k0),
                          *(const u64*)(xr + EMB_D + k0),
                    f2fma(*(const u64*)(xr + k0 + 2),
                          *(const u64*)(xr + EMB_D + k0 + 2), 0ull));
            float lo, hi; f2up(p, lo, hi);
            s[i] = lo + hi;
        }
    }

    // relu + w2 contraction: sum the (even,odd) K halves BEFORE the relu
    #pragma unroll
    for (int m = 0; m < 8; m++) {
        int j    = tx + 16 * m;
        float bj = b1s[j];
        float wj = w2s[j];
        #pragma unroll
        for (int i = 0; i < 4; i++) {
            float lo, hi; f2up(acc[m][i], lo, hi);
            float h = lo + hi + bj;
            s[i] += fmaxf(h, 0.0f) * wj;
        }
    }

    // reduce across the 16 tx lanes (xor < 16 stays within each half-warp)
    #pragma unroll
    for (int off = 1; off < 16; off <<= 1)
        #pragma unroll
        for (int i = 0; i < 4; i++)
            s[i] += __shfl_xor_sync(0xFFFFFFFFu, s[i], off);

    // tx == 0 of each row group writes its 4 rows
    if (tx == 0) {
        float gb = global_bias[0] + b2[0];
        #pragma unroll
        for (int i = 0; i < 4; i++) {
            int r   = ty * 4 + i;
            int row = base + r;
            if (row < B)
                out[row] = s[i] + gb + bsu[r] + bsi[r];
        }
    }
}

extern "C" void kernel_launch(void* const* d_in, const int* in_sizes, int n_in,
                              void* d_out, int out_size)
{
    const int*   users       = (const int*)  d_in[0];
    const int*   items       = (const int*)  d_in[1];
    const float* user_emb    = (const float*)d_in[2];
    const float* item_emb    = (const float*)d_in[3];
    const float* user_bias   = (const float*)d_in[4];
    const float* item_bias   = (const float*)d_in[5];
    const float* global_bias = (const float*)d_in[6];
    const float* w1          = (const float*)d_in[7];
    const float* b1          = (const float*)d_in[8];
    const float* w2          = (const float*)d_in[9];
    const float* b2          = (const float*)d_in[10];
    float*       out         = (float*)d_out;

    int B = in_sizes[0];
    int grid = (B + TM - 1) / TM;   // 256 for B=16384

    cudaFuncSetAttribute(mf_fused_kernel,
                         cudaFuncAttributeMaxDynamicSharedMemorySize,
                         (int)SM_BYTES);

    mf_fused_kernel<<<grid, NTHR, SM_BYTES>>>(
        users, items, user_emb, item_emb, user_bias, item_bias, global_bias,
        w1, b1, w2, b2, out, B);
}

// round 15
// speedup vs baseline: 1.7268x; 1.7268x over previous
#include <cuda_runtime.h>
#include <cuda_bf16.h>
#include <cstdint>

// Problem constants (fixed by the reference)
#define EMB_D  64
#define HID    128
#define KDIM   128
#define TM     128      // batch rows per CTA -> grid = 128
#define NTHR   256      // 8 warps
#define P      136      // tile pitch in bf16 elements (272 B rows, conflict-free)
#define UP     66       // user-vec scratch pitch in floats (conflict-free)

// ---- smem layout (bytes) ----
#define TILE_B   (TM * P * 2)            // 34816
#define SMB_AH   0
#define SMB_AL   (SMB_AH + TILE_B)
#define SMB_WH   (SMB_AL + TILE_B)
#define SMB_WL   (SMB_WH + TILE_B)
#define SMB_USCR (SMB_WL + TILE_B)       // float[128][UP]
#define SMB_B1   (SMB_USCR + 128 * UP * 4)
#define SMB_W2   (SMB_B1 + 512)
#define SMB_DOTS (SMB_W2 + 512)
#define SMB_BSU  (SMB_DOTS + 512)
#define SMB_BSI  (SMB_BSU + 512)
#define SMB_PP   (SMB_BSI + 512)         // float[2][128]
#define SM_BYTES (SMB_PP + 1024)         // ~176.6 KB

__device__ __forceinline__ uint32_t bf2pack(float a, float b) {
    __nv_bfloat162 t = __floats2bfloat162_rn(a, b);   // a -> low, b -> high
    return *reinterpret_cast<uint32_t*>(&t);
}

// Store 8 consecutive floats into hi/lo bf16 tiles (row-major, pitch P).
__device__ __forceinline__ void store8(char* smem, int row, int col0,
                                       const float* v) {
    uint4 H, L;
    float h[8];
    #pragma unroll
    for (int i = 0; i < 8; i++)
        h[i] = __bfloat162float(__float2bfloat16(v[i]));
    H.x = bf2pack(h[0], h[1]); H.y = bf2pack(h[2], h[3]);
    H.z = bf2pack(h[4], h[5]); H.w = bf2pack(h[6], h[7]);
    L.x = bf2pack(v[0] - h[0], v[1] - h[1]);
    L.y = bf2pack(v[2] - h[2], v[3] - h[3]);
    L.z = bf2pack(v[4] - h[4], v[5] - h[5]);
    L.w = bf2pack(v[6] - h[6], v[7] - h[7]);
    uint32_t off = (uint32_t)(row * P + col0) * 2;    // 16B aligned (col0 % 8 == 0)
    *reinterpret_cast<uint4*>(smem + SMB_AH + off) = H;   // caller passes A-rel or W-rel
    *reinterpret_cast<uint4*>(smem + SMB_AL + off) = L;
}
__device__ __forceinline__ void store8w(char* smem, int row, int col0,
                                        const float* v) {
    uint4 H, L;
    float h[8];
    #pragma unroll
    for (int i = 0; i < 8; i++)
        h[i] = __bfloat162float(__float2bfloat16(v[i]));
    H.x = bf2pack(h[0], h[1]); H.y = bf2pack(h[2], h[3]);
    H.z = bf2pack(h[4], h[5]); H.w = bf2pack(h[6], h[7]);
    L.x = bf2pack(v[0] - h[0], v[1] - h[1]);
    L.y = bf2pack(v[2] - h[2], v[3] - h[3]);
    L.z = bf2pack(v[4] - h[4], v[5] - h[5]);
    L.w = bf2pack(v[6] - h[6], v[7] - h[7]);
    uint32_t off = (uint32_t)(row * P + col0) * 2;
    *reinterpret_cast<uint4*>(smem + SMB_WH + off) = H;
    *reinterpret_cast<uint4*>(smem + SMB_WL + off) = L;
}

__device__ __forceinline__ uint32_t lds_u32(const char* tile, int row, int col) {
    return *reinterpret_cast<const uint32_t*>(tile + (uint32_t)(row * P + col) * 2);
}

__device__ __forceinline__ void mma_bf16(float* c, const uint32_t* a,
                                         const uint32_t* b) {
    asm volatile(
        "mma.sync.aligned.m16n8k16.row.col.f32.bf16.bf16.f32 "
        "{%0,%1,%2,%3}, {%4,%5,%6,%7}, {%8,%9}, {%0,%1,%2,%3};"
        : "+f"(c[0]), "+f"(c[1]), "+f"(c[2]), "+f"(c[3])
        : "r"(a[0]), "r"(a[1]), "r"(a[2]), "r"(a[3]), "r"(b[0]), "r"(b[1]));
}

extern "C" __global__ void __launch_bounds__(NTHR, 1)
mf_mma_kernel(const int* __restrict__ users,
              const int* __restrict__ items,
              const float* __restrict__ user_emb,
              const float* __restrict__ item_emb,
              const float* __restrict__ user_bias,
              const float* __restrict__ item_bias,
              const float* __restrict__ global_bias,
              const float* __restrict__ w1,
              const float* __restrict__ b1,
              const float* __restrict__ w2,
              const float* __restrict__ b2,
              float* __restrict__ out,
              int B)
{
    extern __shared__ char smem[];
    float* uscr = (float*)(smem + SMB_USCR);
    float* b1s  = (float*)(smem + SMB_B1);
    float* w2s  = (float*)(smem + SMB_W2);
    float* dots = (float*)(smem + SMB_DOTS);
    float* bsu  = (float*)(smem + SMB_BSU);
    float* bsi  = (float*)(smem + SMB_BSI);
    float* pp   = (float*)(smem + SMB_PP);   // [2][128]

    const int tid  = threadIdx.x;
    const int base = blockIdx.x * TM;

    if (tid < HID) { b1s[tid] = b1[tid]; w2s[tid] = w2[tid]; }

    // ---- stage w1: thread t handles row j = t>>1, k-half (t&1)*64 ----
    {
        int j  = tid >> 1;
        int kh = (tid & 1) * 64;
        const float* wrow = w1 + (size_t)j * KDIM + kh;
        #pragma unroll
        for (int c = 0; c < 64; c += 8) {
            float v[8];
            float4 a = *(const float4*)(wrow + c);
            float4 bq = *(const float4*)(wrow + c + 4);
            v[0]=a.x; v[1]=a.y; v[2]=a.z; v[3]=a.w;
            v[4]=bq.x; v[5]=bq.y; v[6]=bq.z; v[7]=bq.w;
            store8w(smem, j, kh + c, v);
        }
    }

    // ---- gather embeddings: thread t -> row r = t>>1, half = t&1 ----
    const int r    = tid >> 1;
    const int half = tid & 1;
    float myvec[EMB_D];
    {
        int row = base + r;
        int idx = 0;
        if (row < B) idx = half ? items[row] : users[row];
        const float* src = (half ? item_emb : user_emb) + (size_t)idx * EMB_D;
        #pragma unroll
        for (int c = 0; c < EMB_D; c += 4) {
            float4 a = *(const float4*)(src + c);
            myvec[c]=a.x; myvec[c+1]=a.y; myvec[c+2]=a.z; myvec[c+3]=a.w;
        }
        #pragma unroll
        for (int c = 0; c < EMB_D; c += 8)
            store8(smem, r, half * EMB_D + c, myvec + c);  // user->cols 0..63, item->64..127
        if (half == 0) {
            #pragma unroll
            for (int c = 0; c < EMB_D; c += 2)
                *(float2*)(uscr + r * UP + c) = make_float2(myvec[c], myvec[c + 1]);
            bsu[r] = (row < B) ? user_bias[idx] : 0.0f;
        } else {
            bsi[r] = (row < B) ? item_bias[idx] : 0.0f;
        }
    }
    __syncthreads();

    // ---- dot product (item-half threads): exact fp32 ----
    if (half == 1) {
        float dt = 0.0f;
        const float* ur = uscr + r * UP;
        #pragma unroll
        for (int c = 0; c < EMB_D; c += 2) {
            float2 u2 = *(const float2*)(ur + c);
            dt += u2.x * myvec[c] + u2.y * myvec[c + 1];
        }
        dots[r] = dt;
    }

    // ---- mma mainloop ----
    // warp w: mg = w>>1 (rows mg*32..+31), nh = w&1 (cols nh*64..+63)
    const int lane = tid & 31;
    const int warp = tid >> 5;
    const int mbase = (warp >> 1) * 32;
    const int nbase = (warp & 1) * 64;
    const int g  = lane >> 2;
    const int t4 = lane & 3;

    float acc[2][8][4];
    #pragma unroll
    for (int mt = 0; mt < 2; mt++)
        #pragma unroll
        for (int nt = 0; nt < 8; nt++)
            #pragma unroll
            for (int i = 0; i < 4; i++)
                acc[mt][nt][i] = 0.0f;

    #pragma unroll 1
    for (int pass = 0; pass < 3; pass++) {
        const char* At = smem + ((pass == 1) ? SMB_AL : SMB_AH);
        const char* Wt = smem + ((pass == 2) ? SMB_WL : SMB_WH);
        #pragma unroll
        for (int ks = 0; ks < 8; ks++) {
            const int k0 = ks * 16 + 2 * t4;
            uint32_t a[2][4], b[8][2];
            #pragma unroll
            for (int mt = 0; mt < 2; mt++) {
                int r0 = mbase + mt * 16 + g;
                a[mt][0] = lds_u32(At, r0,     k0);
                a[mt][1] = lds_u32(At, r0 + 8, k0);
                a[mt][2] = lds_u32(At, r0,     k0 + 8);
                a[mt][3] = lds_u32(At, r0 + 8, k0 + 8);
            }
            #pragma unroll
            for (int nt = 0; nt < 8; nt++) {
                int n = nbase + nt * 8 + g;
                b[nt][0] = lds_u32(Wt, n, k0);
                b[nt][1] = lds_u32(Wt, n, k0 + 8);
            }
            #pragma unroll
            for (int mt = 0; mt < 2; mt++)
                #pragma unroll
                for (int nt = 0; nt < 8; nt++)
                    mma_bf16(acc[mt][nt], a[mt], b[nt]);
        }
    }

    // ---- epilogue: relu + w2 contraction over this warp's 64 cols ----
    float s[2][2] = {{0.f, 0.f}, {0.f, 0.f}};   // [mt][row-half: g / g+8]
    #pragma unroll
    for (int nt = 0; nt < 8; nt++) {
        int j0 = nbase + nt * 8 + 2 * t4;
        float bj0 = b1s[j0],     wj0 = w2s[j0];
        float bj1 = b1s[j0 + 1], wj1 = w2s[j0 + 1];
        #pragma unroll
        for (int mt = 0; mt < 2; mt++) {
            s[mt][0] += fmaxf(acc[mt][nt][0] + bj0, 0.f) * wj0
                      + fmaxf(acc[mt][nt][1] + bj1, 0.f) * wj1;
            s[mt][1] += fmaxf(acc[mt][nt][2] + bj0, 0.f) * wj0
                      + fmaxf(acc[mt][nt][3] + bj1, 0.f) * wj1;
        }
    }
    // reduce over the 4 lanes of each quad (different cols, same rows)
    #pragma unroll
    for (int mt = 0; mt < 2; mt++)
        #pragma unroll
        for (int h2 = 0; h2 < 2; h2++) {
            s[mt][h2] += __shfl_xor_sync(0xFFFFFFFFu, s[mt][h2], 1);
            s[mt][h2] += __shfl_xor_sync(0xFFFFFFFFu, s[mt][h2], 2);
        }
    if (t4 == 0) {
        int nh = warp & 1;
        #pragma unroll
        for (int mt = 0; mt < 2; mt++) {
            pp[nh * 128 + mbase + mt * 16 + g]     = s[mt][0];
            pp[nh * 128 + mbase + mt * 16 + g + 8] = s[mt][1];
        }
    }
    __syncthreads();

    // ---- final combine (one thread per row) ----
    if (tid < TM) {
        int row = base + tid;
        if (row < B) {
            float v = pp[tid] + pp[128 + tid]
                    + dots[tid] + bsu[tid] + bsi[tid]
                    + global_bias[0] + b2[0];
            out[row] = v;
        }
    }
}

extern "C" void kernel_launch(void* const* d_in, const int* in_sizes, int n_in,
                              void* d_out, int out_size)
{
    const int*   users       = (const int*)  d_in[0];
    const int*   items       = (const int*)  d_in[1];
    const float* user_emb    = (const float*)d_in[2];
    const float* item_emb    = (const float*)d_in[3];
    const float* user_bias   = (const float*)d_in[4];
    const float* item_bias   = (const float*)d_in[5];
    const float* global_bias = (const float*)d_in[6];
    const float* w1          = (const float*)d_in[7];
    const float* b1          = (const float*)d_in[8];
    const float* w2          = (const float*)d_in[9];
    const float* b2          = (const float*)d_in[10];
    float*       out         = (float*)d_out;

    int B = in_sizes[0];
    int grid = (B + TM - 1) / TM;   // 128 for B=16384

    cudaFuncSetAttribute(mf_mma_kernel,
                         cudaFuncAttributeMaxDynamicSharedMemorySize,
                         (int)SM_BYTES);

    mf_mma_kernel<<<grid, NTHR, SM_BYTES>>>(
        users, items, user_emb, item_emb, user_bias, item_bias, global_bias,
        w1, b1, w2, b2, out, B);
}